// round 12
// baseline (speedup 1.0000x reference)
#include <cuda_runtime.h>
#include <math.h>

// ChamferLoss: bs=4, npts=4096, dim=3.
// dist^2(q,r) = ||q||^2 + (||r||^2 - 2 q.r); minimize squared dist, sqrt once.
// At the FFMA2 rt=3 register-bank wall -> only lever left is full-chip occupancy:
// RS=32 ref splits -> 1024 blocks (~7 waves over any SM count, 98.8% efficiency)
// vs the old 128-block single wave that idled 20 of 148 SMs.
// Double-buffered smem mainloop (R11); distributed epilogue via self-resetting
// counters (deterministic, graph-replayable).

#define NPTS 4096
#define BS   4
#define TPB  256
#define Q    4                       // queries per thread
#define RS   32                      // reference splits
#define RPB  (NPTS / RS)             // 128 refs per block
#define QPB  (TPB * Q)               // 1024 queries per block
#define NQT  (NPTS / QPB)            // 4 query tiles
#define NGRP (NQT * BS * 2)          // 32 query-tile groups
#define NGROUPS (RPB / 4)            // 32 ref groups per block

__device__ float g_pmin[2 * BS * NPTS * RS];   // [dir][b][q][rs]  (4 MB)
__device__ float g_gsum[NGRP];
__device__ unsigned int g_gc[NGRP];            // zero-init, self-resetting
__device__ unsigned int g_fc;                  // zero-init, self-resetting

typedef unsigned long long ull;

__device__ __forceinline__ ull bcast2(float f) {
    ull v;
    asm("mov.b64 %0, {%1, %1};" : "=l"(v) : "r"(__float_as_uint(f)));
    return v;
}
__device__ __forceinline__ void unpack2(ull v, float& a, float& b) {
    unsigned lo, hi;
    asm("mov.b64 {%0, %1}, %2;" : "=r"(lo), "=r"(hi) : "l"(v));
    a = __uint_as_float(lo); b = __uint_as_float(hi);
}

struct Grp { ull X01, X23, Y01, Y23, Z01, Z23, H01, H23; };

__device__ __forceinline__ void load_grp(Grp& g, unsigned sa) {
    asm("ld.shared.v2.u64 {%0,%1}, [%2];"    : "=l"(g.X01), "=l"(g.X23) : "r"(sa));
    asm("ld.shared.v2.u64 {%0,%1}, [%2+16];" : "=l"(g.Y01), "=l"(g.Y23) : "r"(sa));
    asm("ld.shared.v2.u64 {%0,%1}, [%2+32];" : "=l"(g.Z01), "=l"(g.Z23) : "r"(sa));
    asm("ld.shared.v2.u64 {%0,%1}, [%2+48];" : "=l"(g.H01), "=l"(g.H23) : "r"(sa));
}

__global__ __launch_bounds__(TPB, 1) void chamfer_main(
    const float* __restrict__ x, const float* __restrict__ y, float* __restrict__ out)
{
    __shared__ float s[RPB * 4 + 16];     // 2 KB + 64B pad group (prefetch overrun)
    __shared__ float red[8];
    __shared__ int   s_last;

    const int tid = threadIdx.x;
    const int qt  = blockIdx.x;           // 0..NQT-1
    const int b   = blockIdx.y;           // 0..BS-1
    const int z   = blockIdx.z;           // 0..2*RS-1
    const int dir = z >> 5;               // z / RS
    const int rs  = z & 31;               // z % RS

    const float* __restrict__ q  = dir ? y : x;
    const float* __restrict__ r  = dir ? x : y;
    const float* __restrict__ rb = r + ((size_t)b * NPTS + (size_t)rs * RPB) * 3;

    // Stage this block's reference slice: -2r (SoA groups of 4) and ||r||^2.
    if (tid < RPB) {
        int i = tid;
        float rx = rb[3 * i + 0];
        float ry = rb[3 * i + 1];
        float rz = rb[3 * i + 2];
        float* base = s + ((i >> 2) << 4) + (i & 3);
        base[0]  = -2.0f * rx;
        base[4]  = -2.0f * ry;
        base[8]  = -2.0f * rz;
        base[12] = fmaf(rx, rx, fmaf(ry, ry, rz * rz));
    }
    if (tid >= TPB - 16) s[RPB * 4 + (tid - (TPB - 16))] = 0.0f;   // pad group

    // Q=4 query points per thread (coalesced loads within each k).
    const int qbase = qt * QPB + tid;
    ull bx[Q], by[Q], bz[Q];
    float qsq[Q];
    #pragma unroll
    for (int k = 0; k < Q; ++k) {
        const float* qp = q + ((size_t)b * NPTS + (qbase + k * TPB)) * 3;
        float qx = qp[0], qy = qp[1], qz = qp[2];
        qsq[k] = fmaf(qx, qx, fmaf(qy, qy, qz * qz));
        bx[k] = bcast2(qx); by[k] = bcast2(qy); bz[k] = bcast2(qz);
    }

    __syncthreads();

    unsigned sa = (unsigned)__cvta_generic_to_shared(s);
    float mac[Q][4];
    #pragma unroll
    for (int k = 0; k < Q; ++k) {
        mac[k][0] = 3.402823466e+38f; mac[k][1] = 3.402823466e+38f;
        mac[k][2] = 3.402823466e+38f; mac[k][3] = 3.402823466e+38f;
    }

    Grp A, B;
    load_grp(A, sa);                       // preload group 0

    #define COMPUTE(G)                                                              \
        _Pragma("unroll")                                                           \
        for (int k = 0; k < Q; ++k) {                                               \
            ull t0, t1;                                                             \
            asm("fma.rn.f32x2 %0, %1, %2, %3;" : "=l"(t0)                           \
                : "l"(bz[k]), "l"((G).Z01), "l"((G).H01));                          \
            asm("fma.rn.f32x2 %0, %1, %2, %0;" : "+l"(t0)                           \
                : "l"(by[k]), "l"((G).Y01));                                        \
            asm("fma.rn.f32x2 %0, %1, %2, %0;" : "+l"(t0)                           \
                : "l"(bx[k]), "l"((G).X01));                                        \
            asm("fma.rn.f32x2 %0, %1, %2, %3;" : "=l"(t1)                           \
                : "l"(bz[k]), "l"((G).Z23), "l"((G).H23));                          \
            asm("fma.rn.f32x2 %0, %1, %2, %0;" : "+l"(t1)                           \
                : "l"(by[k]), "l"((G).Y23));                                        \
            asm("fma.rn.f32x2 %0, %1, %2, %0;" : "+l"(t1)                           \
                : "l"(bx[k]), "l"((G).X23));                                        \
            float a0, a1, a2, a3;                                                   \
            unpack2(t0, a0, a1);                                                    \
            unpack2(t1, a2, a3);                                                    \
            mac[k][0] = fminf(mac[k][0], a0);                                       \
            mac[k][1] = fminf(mac[k][1], a1);                                       \
            mac[k][2] = fminf(mac[k][2], a2);                                       \
            mac[k][3] = fminf(mac[k][3], a3);                                       \
        }

    // Software-pipelined mainloop: loads for g+1 issue before compute of g.
    #pragma unroll 1
    for (int g = 0; g < NGROUPS; g += 2) {
        load_grp(B, sa + 64);              // prefetch g+1
        COMPUTE(A);                        // compute g
        load_grp(A, sa + 128);             // prefetch g+2 (pad group on last iter)
        COMPUTE(B);                        // compute g+1
        sa += 128;
    }
    #undef COMPUTE

    // Write per-query partial (qsq + min over this ref slice).
    const size_t obase = (size_t)(dir * BS + b) * NPTS;
    #pragma unroll
    for (int k = 0; k < Q; ++k) {
        float m = fminf(fminf(mac[k][0], mac[k][1]), fminf(mac[k][2], mac[k][3]));
        g_pmin[(obase + (qbase + k * TPB)) * RS + rs] = qsq[k] + m;
    }

    // ---- Distributed epilogue: last RS-block of each group combines. ----
    const int gidx = (dir * BS + b) * NQT + qt;
    __threadfence();
    if (tid == 0)
        s_last = (atomicAdd(&g_gc[gidx], 1u) == RS - 1) ? 1 : 0;
    __syncthreads();

    if (s_last) {
        if (tid == 0) g_gc[gidx] = 0;     // self-reset for graph replay
        float v = 0.0f;
        #pragma unroll
        for (int k = 0; k < Q; ++k) {
            const float4* pm = (const float4*)&g_pmin[(obase + (qbase + k * TPB)) * RS];
            float m = 3.402823466e+38f;
            #pragma unroll
            for (int j = 0; j < RS / 4; ++j) {
                float4 p = __ldcg(pm + j);
                m = fminf(m, fminf(fminf(p.x, p.y), fminf(p.z, p.w)));
            }
            v += sqrtf(1e-6f + m);
        }
        #pragma unroll
        for (int off = 16; off; off >>= 1)
            v += __shfl_down_sync(0xFFFFFFFFu, v, off);
        if ((tid & 31) == 0) red[tid >> 5] = v;
        __syncthreads();
        if (tid == 0) {
            float t = 0.0f;
            #pragma unroll
            for (int i = 0; i < 8; ++i) t += red[i];
            g_gsum[gidx] = t;
            __threadfence();
            if (atomicAdd(&g_fc, 1u) == NGRP - 1) {
                float tot = 0.0f;
                volatile float* gs = g_gsum;
                #pragma unroll
                for (int i = 0; i < NGRP; ++i) tot += gs[i];
                out[0] = tot * (1.0f / 16384.0f);   // (S1 + S2) / (BS * NPTS)
                g_fc = 0;                            // self-reset for graph replay
            }
        }
    }
}

extern "C" void kernel_launch(void* const* d_in, const int* in_sizes, int n_in,
                              void* d_out, int out_size)
{
    const float* x = (const float*)d_in[0];
    const float* y = (const float*)d_in[1];
    float* out = (float*)d_out;

    chamfer_main<<<dim3(NQT, BS, 2 * RS), TPB>>>(x, y, out);
}